// round 1
// baseline (speedup 1.0000x reference)
#include <cuda_runtime.h>

#define N_NODES 50000
#define N_EDGES 800000
#define IN_DIM 64
#define HID 128
#define NUM_LAYERS 4
#define NUM_GRAPHS 128

// ---------------- scratch (device globals; no allocation allowed) ----------------
__device__ __align__(16) float g_h[N_NODES * HID];     // node features
__device__ __align__(16) float g_aggr[N_NODES * HID];  // edge aggregation, reused as z (gemm2 out)
__device__ __align__(16) float g_t[N_NODES * HID];     // gemm1 intermediate
__device__ __align__(16) float g_vn[NUM_GRAPHS * HID];
__device__ __align__(16) float g_vnup[NUM_GRAPHS * HID];
__device__ double g_bnsum[HID];
__device__ double g_bnsq[HID];
__device__ __align__(16) float g_bnscale[HID];
__device__ __align__(16) float g_bnshift[HID];
__device__ __align__(16) float g_gsum[NUM_GRAPHS * HID];
__device__ int g_cnt[NUM_GRAPHS];

// vector reduction (no return) to global: red.global.add.v4.f32
__device__ __forceinline__ void red_add_v4(float* addr, float4 v) {
    asm volatile("red.global.add.v4.f32 [%0], {%1,%2,%3,%4};"
                 :: "l"(addr), "f"(v.x), "f"(v.y), "f"(v.z), "f"(v.w) : "memory");
}

// ---------------- input projection: h = x @ W_in + b_in ----------------
// 64 nodes per block, 256 threads; thread = 8 nodes x 4 features.
__global__ void k_input(const float* __restrict__ x, const float* __restrict__ Win,
                        const float* __restrict__ bin) {
    __shared__ float xs[64 * 64];    // 16 KB
    __shared__ float ws[64 * 128];   // 32 KB
    int tid = threadIdx.x;
    int base = blockIdx.x * 64;

    const float4* W4 = (const float4*)Win;
    float4* ws4 = (float4*)ws;
#pragma unroll
    for (int i = 0; i < 8; i++) ws4[i * 256 + tid] = W4[i * 256 + tid];

    const float4* x4 = (const float4*)x;
    float4* xs4 = (float4*)xs;
#pragma unroll
    for (int i = 0; i < 4; i++) {
        int idx = i * 256 + tid;
        int n = idx >> 4;
        float4 v = make_float4(0.f, 0.f, 0.f, 0.f);
        if (base + n < N_NODES) v = x4[base * 16 + idx];
        xs4[idx] = v;
    }
    __syncthreads();

    int fg = tid & 31, ng = tid >> 5;
    float4 acc[8];
#pragma unroll
    for (int m = 0; m < 8; m++) acc[m] = make_float4(0.f, 0.f, 0.f, 0.f);
    for (int k = 0; k < 64; k++) {
        float4 w = ((float4*)ws)[k * 32 + fg];
#pragma unroll
        for (int m = 0; m < 8; m++) {
            float uv = xs[(ng + 8 * m) * 64 + k];
            acc[m].x += uv * w.x; acc[m].y += uv * w.y;
            acc[m].z += uv * w.z; acc[m].w += uv * w.w;
        }
    }
    float4 b = ((const float4*)bin)[fg];
    float4* h4 = (float4*)g_h;
#pragma unroll
    for (int m = 0; m < 8; m++) {
        int n = base + ng + 8 * m;
        if (n < N_NODES) {
            float4 o = make_float4(acc[m].x + b.x, acc[m].y + b.y,
                                   acc[m].z + b.z, acc[m].w + b.w);
            h4[n * 32 + fg] = o;
        }
    }
    // one block initializes the small aux buffers (consumed only by later kernels)
    if (blockIdx.x == 0) {
        for (int i = tid; i < NUM_GRAPHS * HID; i += 256) {
            g_vn[i] = 0.f; g_vnup[i] = 0.f; g_gsum[i] = 0.f;
        }
        if (tid < HID) { g_bnsum[tid] = 0.0; g_bnsq[tid] = 0.0; }
        if (tid < NUM_GRAPHS) g_cnt[tid] = 0;
    }
}

// ---------------- per-layer prologue: h += vn[batch]; aggr = 0; bn stats = 0 --------
__global__ void k_pre(const int* __restrict__ batch) {
    int idx = blockIdx.x * 256 + threadIdx.x;  // exactly N_NODES*32
    int node = idx >> 5;
    float4 v = ((const float4*)g_vn)[batch[node] * 32 + (idx & 31)];
    float4 h = ((float4*)g_h)[idx];
    h.x += v.x; h.y += v.y; h.z += v.z; h.w += v.w;
    ((float4*)g_h)[idx] = h;
    ((float4*)g_aggr)[idx] = make_float4(0.f, 0.f, 0.f, 0.f);
    if (blockIdx.x == 0 && threadIdx.x < HID) {
        g_bnsum[threadIdx.x] = 0.0; g_bnsq[threadIdx.x] = 0.0;
    }
}

// ---------------- edge kernel: aggr[dst] += relu(h[src] + edge_attr@W_e + b_e) -------
// one warp per edge; e recomputed on the fly (2 FMAs/elem) instead of reading 410 MB.
__global__ void k_edge(const int* __restrict__ ei, const float* __restrict__ ea,
                       const float* __restrict__ We, const float* __restrict__ be) {
    __shared__ float swe[3 * HID];  // We row0, We row1, b_e
    int tid = threadIdx.x;
    if (tid < 2 * HID) swe[tid] = We[tid];
    if (tid < HID) swe[2 * HID + tid] = be[tid];
    __syncthreads();
    int e = blockIdx.x * 8 + (tid >> 5);   // grid is exactly N_EDGES/8
    int lane = tid & 31;
    int src = ei[e];
    int dst = ei[N_EDGES + e];
    float2 a = ((const float2*)ea)[e];
    float4 w0 = ((float4*)swe)[lane];
    float4 w1 = ((float4*)(swe + HID))[lane];
    float4 bb = ((float4*)(swe + 2 * HID))[lane];
    float4 h = ((const float4*)g_h)[src * 32 + lane];
    float4 m;
    m.x = fmaxf(h.x + a.x * w0.x + a.y * w1.x + bb.x, 0.f);
    m.y = fmaxf(h.y + a.x * w0.y + a.y * w1.y + bb.y, 0.f);
    m.z = fmaxf(h.z + a.x * w0.z + a.y * w1.z + bb.z, 0.f);
    m.w = fmaxf(h.w + a.x * w0.w + a.y * w1.w + bb.w, 0.f);
    red_add_v4(g_aggr + dst * HID + lane * 4, m);
}

// ---------------- node MLP GEMMs (50000x128 @ 128x128) ----------------
// MODE 0: t = relu((h + aggr) @ W1 + b1)      (in: g_h + g_aggr, out: g_t)
// MODE 1: z = t @ W2 + b2, + BN partial stats (in: g_t, out: g_aggr)
template <int MODE>
__global__ void k_gemm(const float* __restrict__ W, const float* __restrict__ bias) {
    __shared__ float u[64 * 128];   // 32 KB (also reused as reduction scratch)
    __shared__ float wb[32 * 128];  // 16 KB
    int tid = threadIdx.x;
    int base = blockIdx.x * 64;

    const float* in1 = (MODE == 0) ? g_h : g_t;
    float* out = (MODE == 0) ? g_t : g_aggr;

    float4* u4 = (float4*)u;
#pragma unroll
    for (int i = 0; i < 8; i++) {
        int idx = i * 256 + tid;
        int n = idx >> 5;
        float4 v = make_float4(0.f, 0.f, 0.f, 0.f);
        if (base + n < N_NODES) {
            v = ((const float4*)in1)[base * 32 + idx];
            if (MODE == 0) {
                float4 v2 = ((const float4*)g_aggr)[base * 32 + idx];
                v.x += v2.x; v.y += v2.y; v.z += v2.z; v.w += v2.w;
            }
        }
        u4[idx] = v;
    }

    int fg = tid & 31, ng = tid >> 5;
    float4 acc[8];
#pragma unroll
    for (int m = 0; m < 8; m++) acc[m] = make_float4(0.f, 0.f, 0.f, 0.f);

    for (int kc = 0; kc < 4; kc++) {
        __syncthreads();
#pragma unroll
        for (int i = 0; i < 4; i++)
            ((float4*)wb)[i * 256 + tid] = ((const float4*)W)[kc * 1024 + i * 256 + tid];
        __syncthreads();
#pragma unroll
        for (int k = 0; k < 32; k++) {
            float4 w = ((float4*)wb)[k * 32 + fg];
#pragma unroll
            for (int m = 0; m < 8; m++) {
                float uv = u[(ng + 8 * m) * 128 + kc * 32 + k];
                acc[m].x += uv * w.x; acc[m].y += uv * w.y;
                acc[m].z += uv * w.z; acc[m].w += uv * w.w;
            }
        }
    }

    float4 b = ((const float4*)bias)[fg];
    float s0 = 0.f, s1 = 0.f, s2 = 0.f, s3 = 0.f;
    float q0 = 0.f, q1 = 0.f, q2 = 0.f, q3 = 0.f;
#pragma unroll
    for (int m = 0; m < 8; m++) {
        int n = base + ng + 8 * m;
        if (n < N_NODES) {
            float4 o = make_float4(acc[m].x + b.x, acc[m].y + b.y,
                                   acc[m].z + b.z, acc[m].w + b.w);
            if (MODE == 0) {
                o.x = fmaxf(o.x, 0.f); o.y = fmaxf(o.y, 0.f);
                o.z = fmaxf(o.z, 0.f); o.w = fmaxf(o.w, 0.f);
            }
            ((float4*)out)[n * 32 + fg] = o;
            if (MODE == 1) {
                s0 += o.x; q0 += o.x * o.x; s1 += o.y; q1 += o.y * o.y;
                s2 += o.z; q2 += o.z * o.z; s3 += o.w; q3 += o.w * o.w;
            }
        }
    }
    if (MODE == 1) {
        __syncthreads();
        float* red = u;  // reuse
        red[tid * 8 + 0] = s0; red[tid * 8 + 1] = s1;
        red[tid * 8 + 2] = s2; red[tid * 8 + 3] = s3;
        red[tid * 8 + 4] = q0; red[tid * 8 + 5] = q1;
        red[tid * 8 + 6] = q2; red[tid * 8 + 7] = q3;
        __syncthreads();
        if (tid < HID) {
            int ffg = tid >> 2, c = tid & 3;
            float S = 0.f, Q = 0.f;
#pragma unroll
            for (int g = 0; g < 8; g++) {
                int src = ((g << 5) + ffg) * 8;
                S += red[src + c];
                Q += red[src + 4 + c];
            }
            atomicAdd(&g_bnsum[tid], (double)S);
            atomicAdd(&g_bnsq[tid], (double)Q);
        }
    }
}

// ---------------- BN stats finalize: scale/shift per feature ----------------
__global__ void k_bnstats(const float* __restrict__ bn_g, const float* __restrict__ bn_b,
                          int layer) {
    int f = threadIdx.x;
    double mu = g_bnsum[f] / (double)N_NODES;
    double var = g_bnsq[f] / (double)N_NODES - mu * mu;
    if (var < 0.0) var = 0.0;
    float sc = bn_g[layer * HID + f] * rsqrtf((float)var + 1e-5f);
    g_bnscale[f] = sc;
    g_bnshift[f] = bn_b[layer * HID + f] - (float)mu * sc;
}

// ---------------- BN apply + relu + (optional) virtual-node sum pool ----------------
__global__ void k_bnapply(const int* __restrict__ batch, int do_pool) {
    int idx = blockIdx.x * 256 + threadIdx.x;  // exactly N_NODES*32
    int node = idx >> 5, j = idx & 31;
    float4 z = ((const float4*)g_aggr)[idx];
    float4 sc = ((const float4*)g_bnscale)[j];
    float4 sh = ((const float4*)g_bnshift)[j];
    float4 h;
    h.x = fmaxf(z.x * sc.x + sh.x, 0.f);
    h.y = fmaxf(z.y * sc.y + sh.y, 0.f);
    h.z = fmaxf(z.z * sc.z + sh.z, 0.f);
    h.w = fmaxf(z.w * sc.w + sh.w, 0.f);
    ((float4*)g_h)[idx] = h;
    if (do_pool) red_add_v4(g_vnup + batch[node] * HID + j * 4, h);
}

// ---------------- virtual-node MLP: vn += mlp(vn_up); vn_up = 0 ----------------
__global__ void k_vn(const float* __restrict__ W1, const float* __restrict__ b1,
                     const float* __restrict__ W2, const float* __restrict__ b2) {
    __shared__ float up[HID];
    __shared__ float t[HID];
    int g = blockIdx.x, j = threadIdx.x;
    up[j] = g_vnup[g * HID + j];
    g_vnup[g * HID + j] = 0.f;
    __syncthreads();
    float s = b1[j];
    for (int k = 0; k < HID; k++) s += up[k] * W1[k * HID + j];
    t[j] = fmaxf(s, 0.f);
    __syncthreads();
    float s2 = b2[j];
    for (int k = 0; k < HID; k++) s2 += t[k] * W2[k * HID + j];
    g_vn[g * HID + j] += s2;
}

// ---------------- final mean-pool accumulation ----------------
__global__ void k_pool(const int* __restrict__ batch) {
    int idx = blockIdx.x * 256 + threadIdx.x;  // exactly N_NODES*32
    int node = idx >> 5, j = idx & 31;
    float4 h = ((const float4*)g_h)[idx];
    red_add_v4(g_gsum + batch[node] * HID + j * 4, h);
    if (j == 0) atomicAdd(&g_cnt[batch[node]], 1);
}

// ---------------- classifier head ----------------
__global__ void k_cls(const float* __restrict__ W1, const float* __restrict__ b1,
                      const float* __restrict__ W2, const float* __restrict__ b2,
                      float* __restrict__ out) {
    __shared__ float gv[HID];
    __shared__ float t[HID];
    __shared__ float red[HID];
    int g = blockIdx.x, j = threadIdx.x;
    float inv = 1.f / fmaxf((float)g_cnt[g], 1.f);
    gv[j] = g_gsum[g * HID + j] * inv;
    __syncthreads();
    float s = b1[j];
    for (int k = 0; k < HID; k++) s += gv[k] * W1[k * HID + j];
    t[j] = fmaxf(s, 0.f);
    __syncthreads();
    red[j] = t[j] * W2[j];
    __syncthreads();
    for (int off = 64; off > 0; off >>= 1) {
        if (j < off) red[j] += red[j + off];
        __syncthreads();
    }
    if (j == 0) out[g] = red[0] + b2[0];
}

// ---------------- host launcher ----------------
extern "C" void kernel_launch(void* const* d_in, const int* in_sizes, int n_in,
                              void* d_out, int out_size) {
    const float* x    = (const float*)d_in[0];
    const float* ea   = (const float*)d_in[1];
    const int*   ei   = (const int*)d_in[2];
    const int*   batch= (const int*)d_in[3];
    const float* W_in = (const float*)d_in[4];
    const float* b_in = (const float*)d_in[5];
    const float* W_e  = (const float*)d_in[6];
    const float* b_e  = (const float*)d_in[7];
    const float* cW1  = (const float*)d_in[8];
    const float* cb1  = (const float*)d_in[9];
    const float* cW2  = (const float*)d_in[10];
    const float* cb2  = (const float*)d_in[11];
    const float* bng  = (const float*)d_in[12];
    const float* bnb  = (const float*)d_in[13];
    const float* vW1  = (const float*)d_in[14];
    const float* vb1  = (const float*)d_in[15];
    const float* vW2  = (const float*)d_in[16];
    const float* vb2  = (const float*)d_in[17];
    const float* clW1 = (const float*)d_in[18];
    const float* clb1 = (const float*)d_in[19];
    const float* clW2 = (const float*)d_in[20];
    const float* clb2 = (const float*)d_in[21];
    float* out = (float*)d_out;

    const int NODE_BLOCKS = (N_NODES + 63) / 64;          // 782
    const int ELEM_BLOCKS = (N_NODES * 32) / 256;         // 6250 (exact)
    const int EDGE_BLOCKS = N_EDGES / 8;                  // 100000 (exact)

    k_input<<<NODE_BLOCKS, 256>>>(x, W_in, b_in);
    for (int L = 0; L < NUM_LAYERS; L++) {
        k_pre<<<ELEM_BLOCKS, 256>>>(batch);
        k_edge<<<EDGE_BLOCKS, 256>>>(ei, ea, W_e, b_e);
        k_gemm<0><<<NODE_BLOCKS, 256>>>(cW1 + L * HID * HID, cb1 + L * HID);
        k_gemm<1><<<NODE_BLOCKS, 256>>>(cW2 + L * HID * HID, cb2 + L * HID);
        k_bnstats<<<1, HID>>>(bng, bnb, L);
        k_bnapply<<<ELEM_BLOCKS, 256>>>(batch, (L != NUM_LAYERS - 1) ? 1 : 0);
        if (L != NUM_LAYERS - 1) k_vn<<<NUM_GRAPHS, HID>>>(vW1, vb1, vW2, vb2);
    }
    k_pool<<<ELEM_BLOCKS, 256>>>(batch);
    k_cls<<<NUM_GRAPHS, HID>>>(clW1, clb1, clW2, clb2, out);
}

// round 2
// speedup vs baseline: 1.2714x; 1.2714x over previous
#include <cuda_runtime.h>

#define N_NODES 50000
#define N_EDGES 800000
#define IN_DIM 64
#define HID 128
#define NUM_LAYERS 4
#define NUM_GRAPHS 128

// ---------------- scratch (device globals; no allocation allowed) ----------------
__device__ __align__(16) float g_h[N_NODES * HID];     // node features
__device__ __align__(16) float g_aggr[N_NODES * HID];  // edge aggregation; reused as z
__device__ __align__(16) float g_vn[NUM_GRAPHS * HID];
__device__ __align__(16) float g_vnup[NUM_GRAPHS * HID];
__device__ double g_bnsum[HID];
__device__ double g_bnsq[HID];
__device__ __align__(16) float g_bnscale[HID];
__device__ __align__(16) float g_bnshift[HID];
__device__ __align__(16) float g_gsum[NUM_GRAPHS * HID];
__device__ int g_gcnt[NUM_GRAPHS];
// CSR (by destination) built once per call
__device__ int g_deg[N_NODES];          // counts, then reused as scatter cursor
__device__ int g_rowptr[N_NODES + 1];
__device__ int g_esrc[N_EDGES];
__device__ __align__(8) float2 g_eatt[N_EDGES];

__device__ __forceinline__ void red_add_v4(float* addr, float4 v) {
    asm volatile("red.global.add.v4.f32 [%0], {%1,%2,%3,%4};"
                 :: "l"(addr), "f"(v.x), "f"(v.y), "f"(v.z), "f"(v.w) : "memory");
}

// ================= CSR build =================
__global__ void k_zero_deg() {
    int i = blockIdx.x * 256 + threadIdx.x;
    if (i < N_NODES) g_deg[i] = 0;
}

__global__ void k_hist(const int* __restrict__ ei) {
    int e = blockIdx.x * 256 + threadIdx.x;   // grid exactly N_EDGES/256
    atomicAdd(&g_deg[ei[N_EDGES + e]], 1);
}

// single block, 1024 threads: exclusive scan of degrees -> rowptr, cursor
__global__ void k_scan() {
    __shared__ int sums[1024];
    int tid = threadIdx.x;
    const int CH = (N_NODES + 1023) / 1024;   // 49
    int st = tid * CH;
    int en = st + CH; if (en > N_NODES) en = N_NODES;
    int s = 0;
    for (int i = st; i < en; i++) s += g_deg[i];
    sums[tid] = s;
    __syncthreads();
    for (int off = 1; off < 1024; off <<= 1) {
        int v = (tid >= off) ? sums[tid - off] : 0;
        __syncthreads();
        sums[tid] += v;
        __syncthreads();
    }
    int run = sums[tid] - s;   // exclusive prefix
    for (int i = st; i < en; i++) {
        int c = g_deg[i];
        g_rowptr[i] = run;
        g_deg[i] = run;        // cursor for scatter
        run += c;
    }
    if (tid == 1023) g_rowptr[N_NODES] = N_EDGES;
}

__global__ void k_scatter(const int* __restrict__ ei, const float* __restrict__ ea) {
    int e = blockIdx.x * 256 + threadIdx.x;   // grid exactly N_EDGES/256
    int d = ei[N_EDGES + e];
    int pos = atomicAdd(&g_deg[d], 1);
    g_esrc[pos] = ei[e];
    g_eatt[pos] = ((const float2*)ea)[e];
}

// ================= input projection: h = x @ W_in + b_in =================
__global__ void k_input(const float* __restrict__ x, const float* __restrict__ Win,
                        const float* __restrict__ bin) {
    __shared__ float xs[64 * 64];
    __shared__ float ws[64 * 128];
    int tid = threadIdx.x;
    int base = blockIdx.x * 64;

    const float4* W4 = (const float4*)Win;
    float4* ws4 = (float4*)ws;
#pragma unroll
    for (int i = 0; i < 8; i++) ws4[i * 256 + tid] = W4[i * 256 + tid];

    const float4* x4 = (const float4*)x;
    float4* xs4 = (float4*)xs;
#pragma unroll
    for (int i = 0; i < 4; i++) {
        int idx = i * 256 + tid;
        int n = idx >> 4;
        float4 v = make_float4(0.f, 0.f, 0.f, 0.f);
        if (base + n < N_NODES) v = x4[base * 16 + idx];
        xs4[idx] = v;
    }
    __syncthreads();

    int fg = tid & 31, ng = tid >> 5;
    float4 acc[8];
#pragma unroll
    for (int m = 0; m < 8; m++) acc[m] = make_float4(0.f, 0.f, 0.f, 0.f);
    for (int k = 0; k < 64; k++) {
        float4 w = ((float4*)ws)[k * 32 + fg];
#pragma unroll
        for (int m = 0; m < 8; m++) {
            float uv = xs[(ng + 8 * m) * 64 + k];
            acc[m].x += uv * w.x; acc[m].y += uv * w.y;
            acc[m].z += uv * w.z; acc[m].w += uv * w.w;
        }
    }
    float4 b = ((const float4*)bin)[fg];
    float4* h4 = (float4*)g_h;
#pragma unroll
    for (int m = 0; m < 8; m++) {
        int n = base + ng + 8 * m;
        if (n < N_NODES) {
            float4 o = make_float4(acc[m].x + b.x, acc[m].y + b.y,
                                   acc[m].z + b.z, acc[m].w + b.w);
            h4[n * 32 + fg] = o;
        }
    }
    if (blockIdx.x == 0) {
        for (int i = tid; i < NUM_GRAPHS * HID; i += 256) {
            g_vn[i] = 0.f; g_vnup[i] = 0.f; g_gsum[i] = 0.f;
        }
        if (tid < HID) { g_bnsum[tid] = 0.0; g_bnsq[tid] = 0.0; }
        if (tid < NUM_GRAPHS) g_gcnt[tid] = 0;
    }
}

// ================= vn broadcast: h += vn[batch]  (layers 1..3 only) =================
__global__ void k_pre(const int* __restrict__ batch) {
    int idx = blockIdx.x * 256 + threadIdx.x;  // exactly N_NODES*32
    int node = idx >> 5;
    float4 v = ((const float4*)g_vn)[batch[node] * 32 + (idx & 31)];
    float4 h = ((float4*)g_h)[idx];
    h.x += v.x; h.y += v.y; h.z += v.z; h.w += v.w;
    ((float4*)g_h)[idx] = h;
}

// ================= edge gather: aggr[n] = sum_{e: dst=n} relu(h[src]+e) ============
// one warp per node, CSR lists; no atomics.
__global__ void k_gather(const float* __restrict__ We, const float* __restrict__ be) {
    int lane = threadIdx.x & 31;
    int n = (blockIdx.x * 256 + threadIdx.x) >> 5;   // grid exactly N_NODES warps
    float4 w0 = ((const float4*)We)[lane];
    float4 w1 = ((const float4*)(We + HID))[lane];
    float4 bb = ((const float4*)be)[lane];
    int start = g_rowptr[n];
    int end = g_rowptr[n + 1];
    float4 acc = make_float4(0.f, 0.f, 0.f, 0.f);
    const float4* h4 = (const float4*)g_h;
    for (int base = start; base < end; base += 32) {
        int idx = base + lane;
        int s = 0;
        float2 a = make_float2(0.f, 0.f);
        if (idx < end) { s = g_esrc[idx]; a = g_eatt[idx]; }
        int cnt = end - base; if (cnt > 32) cnt = 32;
        for (int j = 0; j < cnt; j++) {
            int sj = __shfl_sync(0xffffffffu, s, j);
            float ax = __shfl_sync(0xffffffffu, a.x, j);
            float ay = __shfl_sync(0xffffffffu, a.y, j);
            float4 h = __ldg(&h4[sj * 32 + lane]);
            acc.x += fmaxf(fmaf(ax, w0.x, fmaf(ay, w1.x, h.x + bb.x)), 0.f);
            acc.y += fmaxf(fmaf(ax, w0.y, fmaf(ay, w1.y, h.y + bb.y)), 0.f);
            acc.z += fmaxf(fmaf(ax, w0.z, fmaf(ay, w1.z, h.z + bb.z)), 0.f);
            acc.w += fmaxf(fmaf(ax, w0.w, fmaf(ay, w1.w, h.w + bb.w)), 0.f);
        }
    }
    ((float4*)g_aggr)[n * 32 + lane] = acc;
}

// ================= fused node MLP: z = relu((h+aggr)@W1+b1)@W2+b2, + BN stats ======
// 64 nodes/block, t kept in smem (reuses u buffer); z overwrites g_aggr.
__global__ void __launch_bounds__(256) k_layer_gemm(
    const float* __restrict__ W1, const float* __restrict__ b1,
    const float* __restrict__ W2, const float* __restrict__ b2) {
    __shared__ float u[64 * 128];   // input, then t, then reduction scratch
    __shared__ float wb[32 * 128];
    int tid = threadIdx.x;
    int base = blockIdx.x * 64;
    int fg = tid & 31, ng = tid >> 5;

    float4* u4 = (float4*)u;
#pragma unroll
    for (int i = 0; i < 8; i++) {
        int idx = i * 256 + tid;
        int n = idx >> 5;
        float4 v = make_float4(0.f, 0.f, 0.f, 0.f);
        if (base + n < N_NODES) {
            v = ((const float4*)g_h)[base * 32 + idx];
            float4 v2 = ((const float4*)g_aggr)[base * 32 + idx];
            v.x += v2.x; v.y += v2.y; v.z += v2.z; v.w += v2.w;
        }
        u4[idx] = v;
    }

    float4 acc[8];
#pragma unroll
    for (int m = 0; m < 8; m++) acc[m] = make_float4(0.f, 0.f, 0.f, 0.f);

    // ---- phase 1: t = relu(u @ W1 + b1) ----
    for (int kc = 0; kc < 4; kc++) {
        __syncthreads();
#pragma unroll
        for (int i = 0; i < 4; i++)
            ((float4*)wb)[i * 256 + tid] = ((const float4*)W1)[kc * 1024 + i * 256 + tid];
        __syncthreads();
#pragma unroll
        for (int k = 0; k < 32; k++) {
            float4 w = ((float4*)wb)[k * 32 + fg];
#pragma unroll
            for (int m = 0; m < 8; m++) {
                float uv = u[(ng + 8 * m) * 128 + kc * 32 + k];
                acc[m].x += uv * w.x; acc[m].y += uv * w.y;
                acc[m].z += uv * w.z; acc[m].w += uv * w.w;
            }
        }
    }
    float4 b = ((const float4*)b1)[fg];
    __syncthreads();   // all u reads complete before overwriting with t
#pragma unroll
    for (int m = 0; m < 8; m++) {
        float4 o;
        o.x = fmaxf(acc[m].x + b.x, 0.f);
        o.y = fmaxf(acc[m].y + b.y, 0.f);
        o.z = fmaxf(acc[m].z + b.z, 0.f);
        o.w = fmaxf(acc[m].w + b.w, 0.f);
        u4[(ng + 8 * m) * 32 + fg] = o;
        acc[m] = make_float4(0.f, 0.f, 0.f, 0.f);
    }

    // ---- phase 2: z = t @ W2 + b2 ----
    for (int kc = 0; kc < 4; kc++) {
        __syncthreads();
#pragma unroll
        for (int i = 0; i < 4; i++)
            ((float4*)wb)[i * 256 + tid] = ((const float4*)W2)[kc * 1024 + i * 256 + tid];
        __syncthreads();
#pragma unroll
        for (int k = 0; k < 32; k++) {
            float4 w = ((float4*)wb)[k * 32 + fg];
#pragma unroll
            for (int m = 0; m < 8; m++) {
                float uv = u[(ng + 8 * m) * 128 + kc * 32 + k];
                acc[m].x += uv * w.x; acc[m].y += uv * w.y;
                acc[m].z += uv * w.z; acc[m].w += uv * w.w;
            }
        }
    }
    b = ((const float4*)b2)[fg];
    float s0 = 0.f, s1 = 0.f, s2 = 0.f, s3 = 0.f;
    float q0 = 0.f, q1 = 0.f, q2 = 0.f, q3 = 0.f;
#pragma unroll
    for (int m = 0; m < 8; m++) {
        int n = base + ng + 8 * m;
        if (n < N_NODES) {
            float4 o = make_float4(acc[m].x + b.x, acc[m].y + b.y,
                                   acc[m].z + b.z, acc[m].w + b.w);
            ((float4*)g_aggr)[n * 32 + fg] = o;   // z
            s0 += o.x; q0 += o.x * o.x; s1 += o.y; q1 += o.y * o.y;
            s2 += o.z; q2 += o.z * o.z; s3 += o.w; q3 += o.w * o.w;
        }
    }
    __syncthreads();
    float* red = u;
    red[tid * 8 + 0] = s0; red[tid * 8 + 1] = s1;
    red[tid * 8 + 2] = s2; red[tid * 8 + 3] = s3;
    red[tid * 8 + 4] = q0; red[tid * 8 + 5] = q1;
    red[tid * 8 + 6] = q2; red[tid * 8 + 7] = q3;
    __syncthreads();
    if (tid < HID) {
        int ffg = tid >> 2, c = tid & 3;
        float S = 0.f, Q = 0.f;
#pragma unroll
        for (int g = 0; g < 8; g++) {
            int src = ((g << 5) + ffg) * 8;
            S += red[src + c];
            Q += red[src + 4 + c];
        }
        atomicAdd(&g_bnsum[tid], (double)S);
        atomicAdd(&g_bnsq[tid], (double)Q);
    }
}

// ================= BN stats finalize (+ reset accumulators for next layer) =========
__global__ void k_bnstats(const float* __restrict__ bn_g, const float* __restrict__ bn_b,
                          int layer) {
    int f = threadIdx.x;
    double mu = g_bnsum[f] / (double)N_NODES;
    double var = g_bnsq[f] / (double)N_NODES - mu * mu;
    if (var < 0.0) var = 0.0;
    float sc = bn_g[layer * HID + f] * rsqrtf((float)var + 1e-5f);
    g_bnscale[f] = sc;
    g_bnshift[f] = bn_b[layer * HID + f] - (float)mu * sc;
    g_bnsum[f] = 0.0;
    g_bnsq[f] = 0.0;
}

// ================= BN apply + relu + pooling (vnup, or gsum+counts for last) =======
__global__ void k_bnapply(const int* __restrict__ batch, int last) {
    int idx = blockIdx.x * 256 + threadIdx.x;  // exactly N_NODES*32
    int node = idx >> 5, j = idx & 31;
    float4 z = ((const float4*)g_aggr)[idx];
    float4 sc = ((const float4*)g_bnscale)[j];
    float4 sh = ((const float4*)g_bnshift)[j];
    float4 h;
    h.x = fmaxf(z.x * sc.x + sh.x, 0.f);
    h.y = fmaxf(z.y * sc.y + sh.y, 0.f);
    h.z = fmaxf(z.z * sc.z + sh.z, 0.f);
    h.w = fmaxf(z.w * sc.w + sh.w, 0.f);
    ((float4*)g_h)[idx] = h;
    int g = batch[node];
    if (!last) {
        red_add_v4(g_vnup + g * HID + j * 4, h);
    } else {
        red_add_v4(g_gsum + g * HID + j * 4, h);
        if (j == 0) atomicAdd(&g_gcnt[g], 1);
    }
}

// ================= virtual-node MLP: vn += mlp(vnup); vnup = 0 =====================
__global__ void k_vn(const float* __restrict__ W1, const float* __restrict__ b1,
                     const float* __restrict__ W2, const float* __restrict__ b2) {
    __shared__ float up[HID];
    __shared__ float t[HID];
    int g = blockIdx.x, j = threadIdx.x;
    up[j] = g_vnup[g * HID + j];
    g_vnup[g * HID + j] = 0.f;
    __syncthreads();
    float s = b1[j];
    for (int k = 0; k < HID; k++) s += up[k] * W1[k * HID + j];
    t[j] = fmaxf(s, 0.f);
    __syncthreads();
    float s2 = b2[j];
    for (int k = 0; k < HID; k++) s2 += t[k] * W2[k * HID + j];
    g_vn[g * HID + j] += s2;
}

// ================= classifier head =================
__global__ void k_cls(const float* __restrict__ W1, const float* __restrict__ b1,
                      const float* __restrict__ W2, const float* __restrict__ b2,
                      float* __restrict__ out) {
    __shared__ float gv[HID];
    __shared__ float t[HID];
    __shared__ float red[HID];
    int g = blockIdx.x, j = threadIdx.x;
    float inv = 1.f / fmaxf((float)g_gcnt[g], 1.f);
    gv[j] = g_gsum[g * HID + j] * inv;
    __syncthreads();
    float s = b1[j];
    for (int k = 0; k < HID; k++) s += gv[k] * W1[k * HID + j];
    t[j] = fmaxf(s, 0.f);
    __syncthreads();
    red[j] = t[j] * W2[j];
    __syncthreads();
    for (int off = 64; off > 0; off >>= 1) {
        if (j < off) red[j] += red[j + off];
        __syncthreads();
    }
    if (j == 0) out[g] = red[0] + b2[0];
}

// ================= host launcher =================
extern "C" void kernel_launch(void* const* d_in, const int* in_sizes, int n_in,
                              void* d_out, int out_size) {
    const float* x    = (const float*)d_in[0];
    const float* ea   = (const float*)d_in[1];
    const int*   ei   = (const int*)d_in[2];
    const int*   batch= (const int*)d_in[3];
    const float* W_in = (const float*)d_in[4];
    const float* b_in = (const float*)d_in[5];
    const float* W_e  = (const float*)d_in[6];
    const float* b_e  = (const float*)d_in[7];
    const float* cW1  = (const float*)d_in[8];
    const float* cb1  = (const float*)d_in[9];
    const float* cW2  = (const float*)d_in[10];
    const float* cb2  = (const float*)d_in[11];
    const float* bng  = (const float*)d_in[12];
    const float* bnb  = (const float*)d_in[13];
    const float* vW1  = (const float*)d_in[14];
    const float* vb1  = (const float*)d_in[15];
    const float* vW2  = (const float*)d_in[16];
    const float* vb2  = (const float*)d_in[17];
    const float* clW1 = (const float*)d_in[18];
    const float* clb1 = (const float*)d_in[19];
    const float* clW2 = (const float*)d_in[20];
    const float* clb2 = (const float*)d_in[21];
    float* out = (float*)d_out;

    const int NODE_BLOCKS = (N_NODES + 63) / 64;      // 782
    const int ELEM_BLOCKS = (N_NODES * 32) / 256;     // 6250 (exact)
    const int WARP_BLOCKS = (N_NODES + 7) / 8;        // 6250 (warp per node)
    const int EDGE_BLOCKS = N_EDGES / 256;            // 3125 (exact)

    // CSR build (once per call)
    k_zero_deg<<<(N_NODES + 255) / 256, 256>>>();
    k_hist<<<EDGE_BLOCKS, 256>>>(ei);
    k_scan<<<1, 1024>>>();
    k_scatter<<<EDGE_BLOCKS, 256>>>(ei, ea);

    k_input<<<NODE_BLOCKS, 256>>>(x, W_in, b_in);
    for (int L = 0; L < NUM_LAYERS; L++) {
        if (L > 0) k_pre<<<ELEM_BLOCKS, 256>>>(batch);
        k_gather<<<WARP_BLOCKS, 256>>>(W_e, b_e);
        k_layer_gemm<<<NODE_BLOCKS, 256>>>(cW1 + L * HID * HID, cb1 + L * HID,
                                           cW2 + L * HID * HID, cb2 + L * HID);
        k_bnstats<<<1, HID>>>(bng, bnb, L);
        k_bnapply<<<ELEM_BLOCKS, 256>>>(batch, (L == NUM_LAYERS - 1) ? 1 : 0);
        if (L != NUM_LAYERS - 1) k_vn<<<NUM_GRAPHS, HID>>>(vW1, vb1, vW2, vb2);
    }
    k_cls<<<NUM_GRAPHS, HID>>>(clW1, clb1, clW2, clb2, out);
}